// round 11
// baseline (speedup 1.0000x reference)
#include <cuda_runtime.h>

#define HH 512
#define WW 512
#define NB 16
#define PLANE (HH*WW)
#define IMG (3*PLANE)
#define R 7
#define K 15
#define TX 128
#define TY 32
#define NTHR 512
#define GX (WW/TX)           // 4
#define GY (HH/TY)           // 16
#define NBLK (GX*GY*NB)      // 1024

#define FRW 160              // full-res loaded region width (16B aligned)
#define FW4 (FRW/4)          // 40 float4 per row-pair item
#define HRH 30               // row-pair items (full-res rows ty0-14 .. ty0+45)
#define CRW 80               // chroma region width
#define LROWS 54             // stored luma rows 1..53 + vy rows 0..31 (in place)
#define CROWS 31
#define NITEM (HRH*FW4)      // 1200

// dynamic smem layout (floats)
#define OFF_DU   (LROWS*FRW)
#define OFF_DV   (OFF_DU + CROWS*CRW)
#define OFF_RED  (OFF_DV + CROWS*CRW)
#define SM_FLOATS (OFF_RED + 48)
#define SM_BYTES (SM_FLOATS * 4)

__device__ float g_acc[3];
__device__ unsigned int g_done;

__device__ __forceinline__ float4 f4sub(float4 a, float4 b) {
    return make_float4(a.x-b.x, a.y-b.y, a.z-b.z, a.w-b.w);
}

template<bool SAFE>
__device__ __forceinline__ void phase1(
    const float* __restrict__ pin, const float* __restrict__ ptg,
    float (*s_dy)[FRW], float (*s_du)[CRW], float (*s_dv)[CRW],
    int tx0, int ty0, int tid)
{
    const float4 Z = make_float4(0.f,0.f,0.f,0.f);
    for (int idx = tid; idx < NITEM; idx += NTHR) {
        int hr  = idx / FW4;
        int hc2 = idx - hr * FW4;
        int fy = ty0 - 2*R + 2*hr;        // even
        int fx = tx0 - 16 + 4*hc2;        // multiple of 4 -> 16B aligned

        int lr0 = 2*hr + 1;               // stored luma row for row 0

        float DrA, DrB, DgA, DgB, DbA, DbB;

        // ---- row 0 ----
        {
            int o = fy * WW + fx;
            bool p = true;
            if (!SAFE) p = (fx >= 0) & (fx < WW) & (fy >= 0) & (fy < HH);
            float4 a, b;
            a = p ? *(const float4*)(pin + o) : Z;
            b = p ? *(const float4*)(ptg + o) : Z;
            float4 dr = f4sub(a, b);
            a = p ? *(const float4*)(pin + PLANE + o) : Z;
            b = p ? *(const float4*)(ptg + PLANE + o) : Z;
            float4 dg = f4sub(a, b);
            a = p ? *(const float4*)(pin + 2*PLANE + o) : Z;
            b = p ? *(const float4*)(ptg + 2*PLANE + o) : Z;
            float4 db = f4sub(a, b);

            float4 y = make_float4(
                0.299f*dr.x + 0.587f*dg.x + 0.114f*db.x,
                0.299f*dr.y + 0.587f*dg.y + 0.114f*db.y,
                0.299f*dr.z + 0.587f*dg.z + 0.114f*db.z,
                0.299f*dr.w + 0.587f*dg.w + 0.114f*db.w);
            if (lr0 <= LROWS - 1) *(float4*)&s_dy[lr0][4*hc2] = y;

            DrA = dr.x + dr.y; DrB = dr.z + dr.w;
            DgA = dg.x + dg.y; DgB = dg.z + dg.w;
            DbA = db.x + db.y; DbB = db.z + db.w;
        }
        // ---- row 1 ----
        {
            int o = (fy + 1) * WW + fx;
            bool p = true;
            if (!SAFE) p = (fx >= 0) & (fx < WW) & (fy + 1 >= 0) & (fy + 1 < HH);
            float4 a, b;
            a = p ? *(const float4*)(pin + o) : Z;
            b = p ? *(const float4*)(ptg + o) : Z;
            float4 dr = f4sub(a, b);
            a = p ? *(const float4*)(pin + PLANE + o) : Z;
            b = p ? *(const float4*)(ptg + PLANE + o) : Z;
            float4 dg = f4sub(a, b);
            a = p ? *(const float4*)(pin + 2*PLANE + o) : Z;
            b = p ? *(const float4*)(ptg + 2*PLANE + o) : Z;
            float4 db = f4sub(a, b);

            float4 y = make_float4(
                0.299f*dr.x + 0.587f*dg.x + 0.114f*db.x,
                0.299f*dr.y + 0.587f*dg.y + 0.114f*db.y,
                0.299f*dr.z + 0.587f*dg.z + 0.114f*db.z,
                0.299f*dr.w + 0.587f*dg.w + 0.114f*db.w);
            if (lr0 + 1 <= LROWS - 1) *(float4*)&s_dy[lr0 + 1][4*hc2] = y;

            DrA += dr.x + dr.y; DrB += dr.z + dr.w;
            DgA += dg.x + dg.y; DgB += dg.z + dg.w;
            DbA += db.x + db.y; DbB += db.z + db.w;
        }

        float2 du = make_float2(
            0.25f * (-0.169f*DrA - 0.331f*DgA + 0.5f *DbA),
            0.25f * (-0.169f*DrB - 0.331f*DgB + 0.5f *DbB));
        float2 dv = make_float2(
            0.25f * ( 0.5f  *DrA - 0.46f *DgA - 0.04f*DbA),
            0.25f * ( 0.5f  *DrB - 0.46f *DgB - 0.04f*DbB));
        *(float2*)&s_du[hr + 1][2*hc2] = du;
        *(float2*)&s_dv[hr + 1][2*hc2] = dv;
    }
}

__global__ __launch_bounds__(NTHR, 4) void yuv_loss_kernel(
    const float* __restrict__ inp, const float* __restrict__ tgt,
    float* __restrict__ out)
{
    extern __shared__ float sm[];
    float (*s_dy)[FRW] = (float (*)[FRW])(sm);
    float (*s_du)[CRW] = (float (*)[CRW])(sm + OFF_DU);
    float (*s_dv)[CRW] = (float (*)[CRW])(sm + OFF_DV);
    float* s_red = sm + OFF_RED;

    const int tid = threadIdx.x;
    const int n   = blockIdx.z;
    const int tx0 = blockIdx.x * TX;
    const int ty0 = blockIdx.y * TY;
    const float* pin = inp + (size_t)n * IMG;
    const float* ptg = tgt + (size_t)n * IMG;

    // ---- Phase 1 ----
    bool interior = (tx0 >= 16) & (tx0 + TX + 16 <= WW) &
                    (ty0 >= 2*R) & (ty0 + TY + 2*R + 2 <= HH);
    if (interior) phase1<true >(pin, ptg, s_dy, s_du, s_dv, tx0, ty0, tid);
    else          phase1<false>(pin, ptg, s_dy, s_du, s_dv, tx0, ty0, tid);
    __syncthreads();

    // ---- Phase 2: vertical 15-tap running sums, in place ----
    // dy region row i at stored row i+1; vy[r] = sum(stored r+8 .. r+22) -> stored row r.
    // Stored row x is read at steps x-22 (+) and x-7 (-), both before overwrite at step x.
    if (tid < 142) {
        int c = tid + 9;
        float s = 0.f;
        #pragma unroll
        for (int j = 8; j <= 22; j++) s += s_dy[j][c];
        s_dy[0][c] = s;
        #pragma unroll 4
        for (int r = 1; r < TY; r++) {
            s += s_dy[r + 22][c] - s_dy[r + 7][c];
            s_dy[r][c] = s;
        }
    } else if (tid < 142 + 156) {     // chroma: 2 ch x 78 cols (cols 1..78)
        int t = tid - 142;
        int ch = (t >= 78);
        int c  = (ch ? t - 78 : t) + 1;
        float (*b)[CRW] = ch ? s_dv : s_du;
        float s = 0.f;
        #pragma unroll
        for (int j = 1; j <= 15; j++) s += b[j][c];
        b[0][c] = s;
        #pragma unroll 5
        for (int r = 1; r < TY/2; r++) {
            s += b[r + 15][c] - b[r][c];
            b[r][c] = s;
        }
    }
    __syncthreads();

    // ---- Phase 3: horizontal 15-tap sliding sums, square, accumulate ----
    float accY = 0.f, accU = 0.f, accV = 0.f;
    {   // luma: 32 rows x 16 segments of 8 outputs
        int row = tid >> 4;
        int c0  = (tid & 15) * 8 + 9;       // output x reads vy cols x+9..x+23
        float s = 0.f;
        #pragma unroll
        for (int j = 0; j < K; j++) s += s_dy[row][c0 + j];
        accY = s * s;
        #pragma unroll
        for (int i = 1; i < 8; i++) {
            s += s_dy[row][c0 + i + K - 1] - s_dy[row][c0 + i - 1];
            accY += s * s;
        }
    }
    {   // chroma: 2 ch x 16 rows x 16 segments of 4 outputs
        int ch  = tid >> 8;
        int rem = tid & 255;
        int row = rem >> 4;
        int c0  = (rem & 15) * 4 + 1;
        float (*v)[CRW] = ch ? s_dv : s_du;
        float s = 0.f;
        #pragma unroll
        for (int j = 0; j < K; j++) s += v[row][c0 + j];
        float a = s * s;
        #pragma unroll
        for (int i = 1; i < 4; i++) {
            s += v[row][c0 + i + K - 1] - v[row][c0 + i - 1];
            a += s * s;
        }
        if (ch) accV = a; else accU = a;
    }

    // ---- block reduction (16 warps) ----
    #pragma unroll
    for (int o = 16; o > 0; o >>= 1) {
        accY += __shfl_down_sync(0xffffffffu, accY, o);
        accU += __shfl_down_sync(0xffffffffu, accU, o);
        accV += __shfl_down_sync(0xffffffffu, accV, o);
    }
    int w = tid >> 5, l = tid & 31;
    if (l == 0) { s_red[w] = accY; s_red[16 + w] = accU; s_red[32 + w] = accV; }
    __syncthreads();
    if (tid == 0) {
        float sy = 0.f, su = 0.f, sv = 0.f;
        #pragma unroll
        for (int i = 0; i < 16; i++) { sy += s_red[i]; su += s_red[16+i]; sv += s_red[32+i]; }
        atomicAdd(&g_acc[0], sy);
        atomicAdd(&g_acc[1], su);
        atomicAdd(&g_acc[2], sv);
        __threadfence();
        unsigned int t = atomicAdd(&g_done, 1u);
        if (t == NBLK - 1) {
            const float invY = 1.0f / ((float)NB * HH * WW);
            const float invC = 1.0f / ((float)NB * (HH/2) * (WW/2));
            out[0] = g_acc[0] * invY + (g_acc[1] + g_acc[2]) * invC;
            g_acc[0] = 0.f; g_acc[1] = 0.f; g_acc[2] = 0.f;
            g_done = 0u;
        }
    }
}

extern "C" void kernel_launch(void* const* d_in, const int* in_sizes, int n_in,
                              void* d_out, int out_size)
{
    const float* inp = (const float*)d_in[0];
    const float* tgt = (const float*)d_in[1];
    float* out = (float*)d_out;

    static int configured = 0;
    if (!configured) {
        cudaFuncSetAttribute(yuv_loss_kernel,
                             cudaFuncAttributeMaxDynamicSharedMemorySize, SM_BYTES);
        configured = 1;
    }

    dim3 grid(GX, GY, NB);
    yuv_loss_kernel<<<grid, NTHR, SM_BYTES>>>(inp, tgt, out);
}

// round 12
// speedup vs baseline: 1.1917x; 1.1917x over previous
#include <cuda_runtime.h>

#define HH 512
#define WW 512
#define NB 16
#define PLANE (HH*WW)
#define IMG (3*PLANE)
#define R 7
#define K 15
#define TX 128
#define TY 32
#define NTHR 512
#define GX (WW/TX)           // 4
#define GY (HH/TY)           // 16
#define NBLK (GX*GY*NB)      // 1024

#define FRW 160              // full-res loaded region width (16B aligned)
#define FW4 (FRW/4)          // 40 float4 per row-pair item
#define HRH 30               // row-pair items
#define CRW 80               // chroma region width
#define LROWS 54             // stored dy rows 1..53 used; vy rows 0..31 in place
#define CROWS 31
#define NITEM (HRH*FW4)      // 1200

// dynamic smem layout (floats)
#define OFF_DU   (LROWS*FRW)
#define OFF_DV   (OFF_DU + CROWS*CRW)
#define OFF_RED  (OFF_DV + CROWS*CRW)
#define SM_FLOATS (OFF_RED + 48)
#define SM_BYTES (SM_FLOATS * 4)

__device__ float g_acc[3];
__device__ unsigned int g_done;

__device__ __forceinline__ float4 f4sub(float4 a, float4 b) {
    return make_float4(a.x-b.x, a.y-b.y, a.z-b.z, a.w-b.w);
}

template<bool SAFE>
__device__ __forceinline__ void phase1(
    const float* __restrict__ pin, const float* __restrict__ ptg,
    float (*s_dy)[FRW], float (*s_du)[CRW], float (*s_dv)[CRW],
    int tx0, int ty0, int tid)
{
    const float4 Z = make_float4(0.f,0.f,0.f,0.f);
    for (int idx = tid; idx < NITEM; idx += NTHR) {
        int hr  = idx / FW4;
        int hc2 = idx - hr * FW4;
        int fy = ty0 - 2*R + 2*hr;        // even
        int fx = tx0 - 16 + 4*hc2;        // multiple of 4 -> 16B aligned

        int o0 = fy * WW + fx;
        int o1 = o0 + WW;

        bool p0 = true, p1 = true;
        if (!SAFE) {
            bool cx = (fx >= 0) & (fx < WW);
            p0 = cx & (fy >= 0)     & (fy < HH);
            p1 = cx & (fy + 1 >= 0) & (fy + 1 < HH);
        }

        // channel R
        float4 a0 = (SAFE || p0) ? *(const float4*)(pin + o0) : Z;
        float4 a1 = (SAFE || p1) ? *(const float4*)(pin + o1) : Z;
        float4 b0 = (SAFE || p0) ? *(const float4*)(ptg + o0) : Z;
        float4 b1 = (SAFE || p1) ? *(const float4*)(ptg + o1) : Z;
        float4 dr0 = f4sub(a0, b0), dr1 = f4sub(a1, b1);
        // channel G
        a0 = (SAFE || p0) ? *(const float4*)(pin + PLANE + o0) : Z;
        a1 = (SAFE || p1) ? *(const float4*)(pin + PLANE + o1) : Z;
        b0 = (SAFE || p0) ? *(const float4*)(ptg + PLANE + o0) : Z;
        b1 = (SAFE || p1) ? *(const float4*)(ptg + PLANE + o1) : Z;
        float4 dg0 = f4sub(a0, b0), dg1 = f4sub(a1, b1);
        // channel B
        a0 = (SAFE || p0) ? *(const float4*)(pin + 2*PLANE + o0) : Z;
        a1 = (SAFE || p1) ? *(const float4*)(pin + 2*PLANE + o1) : Z;
        b0 = (SAFE || p0) ? *(const float4*)(ptg + 2*PLANE + o0) : Z;
        b1 = (SAFE || p1) ? *(const float4*)(ptg + 2*PLANE + o1) : Z;
        float4 db0 = f4sub(a0, b0), db1 = f4sub(a1, b1);

        // luma diffs (8 pixels)
        float4 y0 = make_float4(
            0.299f*dr0.x + 0.587f*dg0.x + 0.114f*db0.x,
            0.299f*dr0.y + 0.587f*dg0.y + 0.114f*db0.y,
            0.299f*dr0.z + 0.587f*dg0.z + 0.114f*db0.z,
            0.299f*dr0.w + 0.587f*dg0.w + 0.114f*db0.w);
        float4 y1 = make_float4(
            0.299f*dr1.x + 0.587f*dg1.x + 0.114f*db1.x,
            0.299f*dr1.y + 0.587f*dg1.y + 0.114f*db1.y,
            0.299f*dr1.z + 0.587f*dg1.z + 0.114f*db1.z,
            0.299f*dr1.w + 0.587f*dg1.w + 0.114f*db1.w);

        // pooled 2x2 chroma diffs (+128 offsets cancel)
        float DrA = dr0.x + dr0.y + dr1.x + dr1.y;
        float DrB = dr0.z + dr0.w + dr1.z + dr1.w;
        float DgA = dg0.x + dg0.y + dg1.x + dg1.y;
        float DgB = dg0.z + dg0.w + dg1.z + dg1.w;
        float DbA = db0.x + db0.y + db1.x + db1.y;
        float DbB = db0.z + db0.w + db1.z + db1.w;

        float2 du = make_float2(
            0.25f * (-0.169f*DrA - 0.331f*DgA + 0.5f *DbA),
            0.25f * (-0.169f*DrB - 0.331f*DgB + 0.5f *DbB));
        float2 dv = make_float2(
            0.25f * ( 0.5f  *DrA - 0.46f *DgA - 0.04f*DbA),
            0.25f * ( 0.5f  *DrB - 0.46f *DgB - 0.04f*DbB));

        int lr0 = 2*hr + 1;               // stored luma rows, keep <= 53
        if (lr0 <= LROWS - 1)     *(float4*)&s_dy[lr0][4*hc2]     = y0;
        if (lr0 + 1 <= LROWS - 1) *(float4*)&s_dy[lr0 + 1][4*hc2] = y1;
        *(float2*)&s_du[hr + 1][2*hc2] = du;
        *(float2*)&s_dv[hr + 1][2*hc2] = dv;
    }
}

__global__ __launch_bounds__(NTHR, 3) void yuv_loss_kernel(
    const float* __restrict__ inp, const float* __restrict__ tgt,
    float* __restrict__ out)
{
    extern __shared__ float sm[];
    float (*s_dy)[FRW] = (float (*)[FRW])(sm);
    float (*s_du)[CRW] = (float (*)[CRW])(sm + OFF_DU);
    float (*s_dv)[CRW] = (float (*)[CRW])(sm + OFF_DV);
    float* s_red = sm + OFF_RED;

    const int tid = threadIdx.x;
    const int n   = blockIdx.z;
    const int tx0 = blockIdx.x * TX;
    const int ty0 = blockIdx.y * TY;
    const float* pin = inp + (size_t)n * IMG;
    const float* ptg = tgt + (size_t)n * IMG;

    // ---- Phase 1 ----
    bool interior = (tx0 >= 16) & (tx0 + TX + 16 <= WW) &
                    (ty0 >= 2*R) & (ty0 + TY + 2*R + 2 <= HH);
    if (interior) phase1<true >(pin, ptg, s_dy, s_du, s_dv, tx0, ty0, tid);
    else          phase1<false>(pin, ptg, s_dy, s_du, s_dv, tx0, ty0, tid);
    __syncthreads();

    // ---- Phase 2: vertical 15-tap running sums, in place (R6-verified windows) ----
    // dy region row i at stored row i+1; vy[r] = sum(stored r+8 .. r+22) -> stored row r.
    // Stored row x read at steps x-22 (+) and x-7 (-), both before its overwrite at step x.
    if (tid < 142) {
        int c = tid + 9;
        float s = 0.f;
        #pragma unroll
        for (int j = 8; j <= 22; j++) s += s_dy[j][c];
        s_dy[0][c] = s;
        #pragma unroll 4
        for (int r = 1; r < TY; r++) {
            s += s_dy[r + 22][c] - s_dy[r + 7][c];
            s_dy[r][c] = s;
        }
    } else if (tid < 142 + 156) {     // chroma: 2 ch x 78 cols (cols 1..78)
        int t = tid - 142;
        int ch = (t >= 78);
        int c  = (ch ? t - 78 : t) + 1;
        float (*b)[CRW] = ch ? s_dv : s_du;
        float s = 0.f;
        #pragma unroll
        for (int j = 1; j <= 15; j++) s += b[j][c];
        b[0][c] = s;
        #pragma unroll 5
        for (int r = 1; r < TY/2; r++) {
            s += b[r + 15][c] - b[r][c];
            b[r][c] = s;
        }
    }
    __syncthreads();

    // ---- Phase 3: horizontal 15-tap sliding sums via vectorized window loads ----
    float accY = 0.f, accU = 0.f, accV = 0.f;
    {   // luma: 32 rows x 16 segments of 8 outputs; window v[c0-1 .. c0+22]
        int row = tid >> 4;
        int c0  = (tid & 15) * 8 + 9;           // c0-1 multiple of 8 -> 16B aligned
        const float* vp = &s_dy[row][c0 - 1];
        float4 q0 = *(const float4*)(vp);       // c0-1..c0+2
        float4 q1 = *(const float4*)(vp + 4);   // c0+3..c0+6
        float4 q2 = *(const float4*)(vp + 8);   // c0+7..c0+10
        float4 q3 = *(const float4*)(vp + 12);  // c0+11..c0+14
        float4 q4 = *(const float4*)(vp + 16);  // c0+15..c0+18
        float4 q5 = *(const float4*)(vp + 20);  // c0+19..c0+22

        float s = ((q0.y + q0.z) + (q0.w + q1.x))
                + ((q1.y + q1.z) + (q1.w + q2.x))
                + ((q2.y + q2.z) + (q2.w + q3.x))
                + ((q3.y + q3.z) + q3.w);
        accY = s * s;
        s += q4.x - q0.y; accY += s * s;
        s += q4.y - q0.z; accY += s * s;
        s += q4.z - q0.w; accY += s * s;
        s += q4.w - q1.x; accY += s * s;
        s += q5.x - q1.y; accY += s * s;
        s += q5.y - q1.z; accY += s * s;
        s += q5.z - q1.w; accY += s * s;
    }
    {   // chroma: 2 ch x 16 rows x 16 segments of 4 outputs; window v[c0-1 .. c0+17]
        int ch  = tid >> 8;
        int rem = tid & 255;
        int row = rem >> 4;
        int c0  = (rem & 15) * 4 + 1;           // c0-1 multiple of 4 -> 16B aligned
        float (*v)[CRW] = ch ? s_dv : s_du;
        const float* vp = &v[row][c0 - 1];
        float4 p0 = *(const float4*)(vp);       // c0-1..c0+2
        float4 p1 = *(const float4*)(vp + 4);   // c0+3..c0+6
        float4 p2 = *(const float4*)(vp + 8);   // c0+7..c0+10
        float4 p3 = *(const float4*)(vp + 12);  // c0+11..c0+14
        float4 p4 = *(const float4*)(vp + 16);  // c0+15..c0+18

        float s = ((p0.y + p0.z) + (p0.w + p1.x))
                + ((p1.y + p1.z) + (p1.w + p2.x))
                + ((p2.y + p2.z) + (p2.w + p3.x))
                + ((p3.y + p3.z) + p3.w);
        float a = s * s;
        s += p4.x - p0.y; a += s * s;
        s += p4.y - p0.z; a += s * s;
        s += p4.z - p0.w; a += s * s;
        if (ch) accV = a; else accU = a;
    }

    // ---- block reduction (16 warps) ----
    #pragma unroll
    for (int o = 16; o > 0; o >>= 1) {
        accY += __shfl_down_sync(0xffffffffu, accY, o);
        accU += __shfl_down_sync(0xffffffffu, accU, o);
        accV += __shfl_down_sync(0xffffffffu, accV, o);
    }
    int w = tid >> 5, l = tid & 31;
    if (l == 0) { s_red[w] = accY; s_red[16 + w] = accU; s_red[32 + w] = accV; }
    __syncthreads();
    if (tid == 0) {
        float sy = 0.f, su = 0.f, sv = 0.f;
        #pragma unroll
        for (int i = 0; i < 16; i++) { sy += s_red[i]; su += s_red[16+i]; sv += s_red[32+i]; }
        atomicAdd(&g_acc[0], sy);
        atomicAdd(&g_acc[1], su);
        atomicAdd(&g_acc[2], sv);
        __threadfence();
        unsigned int t = atomicAdd(&g_done, 1u);
        if (t == NBLK - 1) {
            const float invY = 1.0f / ((float)NB * HH * WW);
            const float invC = 1.0f / ((float)NB * (HH/2) * (WW/2));
            out[0] = g_acc[0] * invY + (g_acc[1] + g_acc[2]) * invC;
            g_acc[0] = 0.f; g_acc[1] = 0.f; g_acc[2] = 0.f;
            g_done = 0u;
        }
    }
}

extern "C" void kernel_launch(void* const* d_in, const int* in_sizes, int n_in,
                              void* d_out, int out_size)
{
    const float* inp = (const float*)d_in[0];
    const float* tgt = (const float*)d_in[1];
    float* out = (float*)d_out;

    static int configured = 0;
    if (!configured) {
        cudaFuncSetAttribute(yuv_loss_kernel,
                             cudaFuncAttributeMaxDynamicSharedMemorySize, SM_BYTES);
        configured = 1;
    }

    dim3 grid(GX, GY, NB);
    yuv_loss_kernel<<<grid, NTHR, SM_BYTES>>>(inp, tgt, out);
}

// round 13
// speedup vs baseline: 1.4865x; 1.2474x over previous
#include <cuda_runtime.h>

#define HH 512
#define WW 512
#define NB 16
#define PLANE (HH*WW)
#define IMG (3*PLANE)
#define R 7
#define K 15
#define TX 128
#define TY 32
#define NTHR 512
#define GX (WW/TX)           // 4
#define GY (HH/TY)           // 16
#define NBLK (GX*GY*NB)      // 1024

#define FRW 160              // full-res loaded region width (16B aligned)
#define FW4 (FRW/4)          // 40 float4 per row-pair item
#define HRH 30               // row-pair items
#define CRW 80               // chroma region width
#define LROWS 54             // stored dy rows 1..53 used; vy rows 0..31 in place
#define CROWS 31
#define NITEM (HRH*FW4)      // 1200

// dynamic smem layout (floats)
#define OFF_DU   (LROWS*FRW)
#define OFF_DV   (OFF_DU + CROWS*CRW)
#define OFF_RED  (OFF_DV + CROWS*CRW)
#define SM_FLOATS (OFF_RED + 48)
#define SM_BYTES (SM_FLOATS * 4)

__device__ float g_acc[3];
__device__ unsigned int g_done;

__device__ __forceinline__ float4 f4sub(float4 a, float4 b) {
    return make_float4(a.x-b.x, a.y-b.y, a.z-b.z, a.w-b.w);
}

template<bool SAFE>
__device__ __forceinline__ void phase1(
    const float* __restrict__ pin, const float* __restrict__ ptg,
    float (*s_dy)[FRW], float (*s_du)[CRW], float (*s_dv)[CRW],
    int tx0, int ty0, int tid)
{
    const float4 Z = make_float4(0.f,0.f,0.f,0.f);
    for (int idx = tid; idx < NITEM; idx += NTHR) {
        int hr  = idx / FW4;
        int hc2 = idx - hr * FW4;
        int fy = ty0 - 2*R + 2*hr;        // even
        int fx = tx0 - 16 + 4*hc2;        // multiple of 4 -> 16B aligned

        int o0 = fy * WW + fx;
        int o1 = o0 + WW;

        bool p0 = true, p1 = true;
        if (!SAFE) {
            bool cx = (fx >= 0) & (fx < WW);
            p0 = cx & (fy >= 0)     & (fy < HH);
            p1 = cx & (fy + 1 >= 0) & (fy + 1 < HH);
        }

        // channel R
        float4 a0 = (SAFE || p0) ? *(const float4*)(pin + o0) : Z;
        float4 a1 = (SAFE || p1) ? *(const float4*)(pin + o1) : Z;
        float4 b0 = (SAFE || p0) ? *(const float4*)(ptg + o0) : Z;
        float4 b1 = (SAFE || p1) ? *(const float4*)(ptg + o1) : Z;
        float4 dr0 = f4sub(a0, b0), dr1 = f4sub(a1, b1);
        // channel G
        a0 = (SAFE || p0) ? *(const float4*)(pin + PLANE + o0) : Z;
        a1 = (SAFE || p1) ? *(const float4*)(pin + PLANE + o1) : Z;
        b0 = (SAFE || p0) ? *(const float4*)(ptg + PLANE + o0) : Z;
        b1 = (SAFE || p1) ? *(const float4*)(ptg + PLANE + o1) : Z;
        float4 dg0 = f4sub(a0, b0), dg1 = f4sub(a1, b1);
        // channel B
        a0 = (SAFE || p0) ? *(const float4*)(pin + 2*PLANE + o0) : Z;
        a1 = (SAFE || p1) ? *(const float4*)(pin + 2*PLANE + o1) : Z;
        b0 = (SAFE || p0) ? *(const float4*)(ptg + 2*PLANE + o0) : Z;
        b1 = (SAFE || p1) ? *(const float4*)(ptg + 2*PLANE + o1) : Z;
        float4 db0 = f4sub(a0, b0), db1 = f4sub(a1, b1);

        // luma diffs (8 pixels)
        float4 y0 = make_float4(
            0.299f*dr0.x + 0.587f*dg0.x + 0.114f*db0.x,
            0.299f*dr0.y + 0.587f*dg0.y + 0.114f*db0.y,
            0.299f*dr0.z + 0.587f*dg0.z + 0.114f*db0.z,
            0.299f*dr0.w + 0.587f*dg0.w + 0.114f*db0.w);
        float4 y1 = make_float4(
            0.299f*dr1.x + 0.587f*dg1.x + 0.114f*db1.x,
            0.299f*dr1.y + 0.587f*dg1.y + 0.114f*db1.y,
            0.299f*dr1.z + 0.587f*dg1.z + 0.114f*db1.z,
            0.299f*dr1.w + 0.587f*dg1.w + 0.114f*db1.w);

        // pooled 2x2 chroma diffs (+128 offsets cancel)
        float DrA = dr0.x + dr0.y + dr1.x + dr1.y;
        float DrB = dr0.z + dr0.w + dr1.z + dr1.w;
        float DgA = dg0.x + dg0.y + dg1.x + dg1.y;
        float DgB = dg0.z + dg0.w + dg1.z + dg1.w;
        float DbA = db0.x + db0.y + db1.x + db1.y;
        float DbB = db0.z + db0.w + db1.z + db1.w;

        float2 du = make_float2(
            0.25f * (-0.169f*DrA - 0.331f*DgA + 0.5f *DbA),
            0.25f * (-0.169f*DrB - 0.331f*DgB + 0.5f *DbB));
        float2 dv = make_float2(
            0.25f * ( 0.5f  *DrA - 0.46f *DgA - 0.04f*DbA),
            0.25f * ( 0.5f  *DrB - 0.46f *DgB - 0.04f*DbB));

        int lr0 = 2*hr + 1;               // stored luma rows, keep <= 53
        if (lr0 <= LROWS - 1)     *(float4*)&s_dy[lr0][4*hc2]     = y0;
        if (lr0 + 1 <= LROWS - 1) *(float4*)&s_dy[lr0 + 1][4*hc2] = y1;
        *(float2*)&s_du[hr + 1][2*hc2] = du;
        *(float2*)&s_dv[hr + 1][2*hc2] = dv;
    }
}

__global__ __launch_bounds__(NTHR, 3) void yuv_loss_kernel(
    const float* __restrict__ inp, const float* __restrict__ tgt,
    float* __restrict__ out)
{
    extern __shared__ float sm[];
    float (*s_dy)[FRW] = (float (*)[FRW])(sm);
    float (*s_du)[CRW] = (float (*)[CRW])(sm + OFF_DU);
    float (*s_dv)[CRW] = (float (*)[CRW])(sm + OFF_DV);
    float* s_red = sm + OFF_RED;

    const int tid = threadIdx.x;
    const int n   = blockIdx.z;
    const int tx0 = blockIdx.x * TX;
    const int ty0 = blockIdx.y * TY;
    const float* pin = inp + (size_t)n * IMG;
    const float* ptg = tgt + (size_t)n * IMG;

    // ---- Phase 1 ----
    bool interior = (tx0 >= 16) & (tx0 + TX + 16 <= WW) &
                    (ty0 >= 2*R) & (ty0 + TY + 2*R + 2 <= HH);
    if (interior) phase1<true >(pin, ptg, s_dy, s_du, s_dv, tx0, ty0, tid);
    else          phase1<false>(pin, ptg, s_dy, s_du, s_dv, tx0, ty0, tid);
    __syncthreads();

    // ---- Phase 2: vertical 15-tap running sums, in place (R6-verified windows) ----
    // dy region row i at stored row i+1; vy[r] = sum(stored r+8 .. r+22) -> stored row r.
    // Stored row x read at steps x-22 (+) and x-7 (-), both before its overwrite at step x.
    if (tid < 142) {
        int c = tid + 9;
        float s = 0.f;
        #pragma unroll
        for (int j = 8; j <= 22; j++) s += s_dy[j][c];
        s_dy[0][c] = s;
        #pragma unroll 4
        for (int r = 1; r < TY; r++) {
            s += s_dy[r + 22][c] - s_dy[r + 7][c];
            s_dy[r][c] = s;
        }
    } else if (tid < 142 + 156) {     // chroma: 2 ch x 78 cols (cols 1..78)
        int t = tid - 142;
        int ch = (t >= 78);
        int c  = (ch ? t - 78 : t) + 1;
        float (*b)[CRW] = ch ? s_dv : s_du;
        float s = 0.f;
        #pragma unroll
        for (int j = 1; j <= 15; j++) s += b[j][c];
        b[0][c] = s;
        #pragma unroll 5
        for (int r = 1; r < TY/2; r++) {
            s += b[r + 15][c] - b[r][c];
            b[r][c] = s;
        }
    }
    __syncthreads();

    // ---- Phase 3: conflict-free direct 15-tap horizontal sums ----
    // Lanes map to CONSECUTIVE columns -> every tap is a coalesced 1-wavefront LDS.
    float accY = 0.f, accU = 0.f, accV = 0.f;
    {   // luma: 32 rows x 128 cols = 4096 outputs, 8 per thread
        #pragma unroll
        for (int p = 0; p < 8; p++) {
            int t   = tid + NTHR * p;     // 0..4095; warp -> same row, consecutive x
            int row = t >> 7;             // 0..31
            int x   = t & 127;
            const float* vp = &s_dy[row][x + 9];   // window: stored cols x+9..x+23
            float s = 0.f;
            #pragma unroll
            for (int j = 0; j < K; j++) s += vp[j];
            accY += s * s;
        }
    }
    {   // chroma: 2 ch x 16 rows x 64 cols = 2048 outputs, 4 per thread
        #pragma unroll
        for (int p = 0; p < 4; p++) {
            int t   = tid + NTHR * p;     // 0..2047
            int ch  = t >> 10;            // warp-uniform per pass
            int row = (t >> 6) & 15;
            int x   = t & 63;
            float (*v)[CRW] = ch ? s_dv : s_du;
            const float* vp = &v[row][x + 1];      // window: stored cols x+1..x+15
            float s = 0.f;
            #pragma unroll
            for (int j = 0; j < K; j++) s += vp[j];
            if (ch) accV += s * s; else accU += s * s;
        }
    }

    // ---- block reduction (16 warps) ----
    #pragma unroll
    for (int o = 16; o > 0; o >>= 1) {
        accY += __shfl_down_sync(0xffffffffu, accY, o);
        accU += __shfl_down_sync(0xffffffffu, accU, o);
        accV += __shfl_down_sync(0xffffffffu, accV, o);
    }
    int w = tid >> 5, l = tid & 31;
    if (l == 0) { s_red[w] = accY; s_red[16 + w] = accU; s_red[32 + w] = accV; }
    __syncthreads();
    if (tid == 0) {
        float sy = 0.f, su = 0.f, sv = 0.f;
        #pragma unroll
        for (int i = 0; i < 16; i++) { sy += s_red[i]; su += s_red[16+i]; sv += s_red[32+i]; }
        atomicAdd(&g_acc[0], sy);
        atomicAdd(&g_acc[1], su);
        atomicAdd(&g_acc[2], sv);
        __threadfence();
        unsigned int t = atomicAdd(&g_done, 1u);
        if (t == NBLK - 1) {
            const float invY = 1.0f / ((float)NB * HH * WW);
            const float invC = 1.0f / ((float)NB * (HH/2) * (WW/2));
            out[0] = g_acc[0] * invY + (g_acc[1] + g_acc[2]) * invC;
            g_acc[0] = 0.f; g_acc[1] = 0.f; g_acc[2] = 0.f;
            g_done = 0u;
        }
    }
}

extern "C" void kernel_launch(void* const* d_in, const int* in_sizes, int n_in,
                              void* d_out, int out_size)
{
    const float* inp = (const float*)d_in[0];
    const float* tgt = (const float*)d_in[1];
    float* out = (float*)d_out;

    static int configured = 0;
    if (!configured) {
        cudaFuncSetAttribute(yuv_loss_kernel,
                             cudaFuncAttributeMaxDynamicSharedMemorySize, SM_BYTES);
        configured = 1;
    }

    dim3 grid(GX, GY, NB);
    yuv_loss_kernel<<<grid, NTHR, SM_BYTES>>>(inp, tgt, out);
}

// round 14
// speedup vs baseline: 1.7371x; 1.1686x over previous
#include <cuda_runtime.h>

#define HH 512
#define WW 512
#define NB 16
#define PLANE (HH*WW)
#define IMG (3*PLANE)
#define R 7
#define K 15
#define TX 128
#define TY 32
#define NTHR 512
#define GX (WW/TX)           // 4
#define GY (HH/TY)           // 16
#define NBLK (GX*GY*NB)      // 1024

#define FRW 161              // luma row stride, ODD -> lane=row phase-3 conflict-free
#define FW4 40               // float4-sized items per row-pair (160 data cols)
#define HRH 30               // row-pair items
#define CRW 82               // chroma row stride (18 mod 32; 16-lane conflict-free)
#define LROWS 54             // stored dy rows 1..53; vy rows 0..31 in place
#define CROWS 31
#define NITEM (HRH*FW4)      // 1200

// dynamic smem layout (floats)
#define OFF_DU   (LROWS*FRW)
#define OFF_DV   (OFF_DU + CROWS*CRW)
#define OFF_RED  (OFF_DV + CROWS*CRW)
#define SM_FLOATS (OFF_RED + 48)
#define SM_BYTES (SM_FLOATS * 4)

__device__ float g_acc[3];
__device__ unsigned int g_done;

__device__ __forceinline__ float4 f4sub(float4 a, float4 b) {
    return make_float4(a.x-b.x, a.y-b.y, a.z-b.z, a.w-b.w);
}

template<bool SAFE>
__device__ __forceinline__ void phase1(
    const float* __restrict__ pin, const float* __restrict__ ptg,
    float (*s_dy)[FRW], float (*s_du)[CRW], float (*s_dv)[CRW],
    int tx0, int ty0, int tid)
{
    const float4 Z = make_float4(0.f,0.f,0.f,0.f);
    for (int idx = tid; idx < NITEM; idx += NTHR) {
        int hr  = idx / FW4;
        int hc2 = idx - hr * FW4;
        int fy = ty0 - 2*R + 2*hr;        // even
        int fx = tx0 - 16 + 4*hc2;        // multiple of 4 -> 16B aligned global

        int o0 = fy * WW + fx;
        int o1 = o0 + WW;

        bool p0 = true, p1 = true;
        if (!SAFE) {
            bool cx = (fx >= 0) & (fx < WW);
            p0 = cx & (fy >= 0)     & (fy < HH);
            p1 = cx & (fy + 1 >= 0) & (fy + 1 < HH);
        }

        // channel R
        float4 a0 = (SAFE || p0) ? *(const float4*)(pin + o0) : Z;
        float4 a1 = (SAFE || p1) ? *(const float4*)(pin + o1) : Z;
        float4 b0 = (SAFE || p0) ? *(const float4*)(ptg + o0) : Z;
        float4 b1 = (SAFE || p1) ? *(const float4*)(ptg + o1) : Z;
        float4 dr0 = f4sub(a0, b0), dr1 = f4sub(a1, b1);
        // channel G
        a0 = (SAFE || p0) ? *(const float4*)(pin + PLANE + o0) : Z;
        a1 = (SAFE || p1) ? *(const float4*)(pin + PLANE + o1) : Z;
        b0 = (SAFE || p0) ? *(const float4*)(ptg + PLANE + o0) : Z;
        b1 = (SAFE || p1) ? *(const float4*)(ptg + PLANE + o1) : Z;
        float4 dg0 = f4sub(a0, b0), dg1 = f4sub(a1, b1);
        // channel B
        a0 = (SAFE || p0) ? *(const float4*)(pin + 2*PLANE + o0) : Z;
        a1 = (SAFE || p1) ? *(const float4*)(pin + 2*PLANE + o1) : Z;
        b0 = (SAFE || p0) ? *(const float4*)(ptg + 2*PLANE + o0) : Z;
        b1 = (SAFE || p1) ? *(const float4*)(ptg + 2*PLANE + o1) : Z;
        float4 db0 = f4sub(a0, b0), db1 = f4sub(a1, b1);

        // luma diffs (8 pixels)
        float4 y0 = make_float4(
            0.299f*dr0.x + 0.587f*dg0.x + 0.114f*db0.x,
            0.299f*dr0.y + 0.587f*dg0.y + 0.114f*db0.y,
            0.299f*dr0.z + 0.587f*dg0.z + 0.114f*db0.z,
            0.299f*dr0.w + 0.587f*dg0.w + 0.114f*db0.w);
        float4 y1 = make_float4(
            0.299f*dr1.x + 0.587f*dg1.x + 0.114f*db1.x,
            0.299f*dr1.y + 0.587f*dg1.y + 0.114f*db1.y,
            0.299f*dr1.z + 0.587f*dg1.z + 0.114f*db1.z,
            0.299f*dr1.w + 0.587f*dg1.w + 0.114f*db1.w);

        // pooled 2x2 chroma diffs (+128 offsets cancel)
        float DrA = dr0.x + dr0.y + dr1.x + dr1.y;
        float DrB = dr0.z + dr0.w + dr1.z + dr1.w;
        float DgA = dg0.x + dg0.y + dg1.x + dg1.y;
        float DgB = dg0.z + dg0.w + dg1.z + dg1.w;
        float DbA = db0.x + db0.y + db1.x + db1.y;
        float DbB = db0.z + db0.w + db1.z + db1.w;

        float2 du = make_float2(
            0.25f * (-0.169f*DrA - 0.331f*DgA + 0.5f *DbA),
            0.25f * (-0.169f*DrB - 0.331f*DgB + 0.5f *DbB));
        float2 dv = make_float2(
            0.25f * ( 0.5f  *DrA - 0.46f *DgA - 0.04f*DbA),
            0.25f * ( 0.5f  *DrB - 0.46f *DgB - 0.04f*DbB));

        // scalar luma stores (FRW odd: no 16B alignment; conflict cost small)
        int lr0 = 2*hr + 1;               // keep rows <= 53
        int cc  = 4*hc2;
        if (lr0 <= LROWS - 1) {
            float* p = &s_dy[lr0][cc];
            p[0] = y0.x; p[1] = y0.y; p[2] = y0.z; p[3] = y0.w;
        }
        if (lr0 + 1 <= LROWS - 1) {
            float* p = &s_dy[lr0 + 1][cc];
            p[0] = y1.x; p[1] = y1.y; p[2] = y1.z; p[3] = y1.w;
        }
        *(float2*)&s_du[hr + 1][2*hc2] = du;
        *(float2*)&s_dv[hr + 1][2*hc2] = dv;
    }
}

__global__ __launch_bounds__(NTHR, 3) void yuv_loss_kernel(
    const float* __restrict__ inp, const float* __restrict__ tgt,
    float* __restrict__ out)
{
    extern __shared__ float sm[];
    float (*s_dy)[FRW] = (float (*)[FRW])(sm);
    float (*s_du)[CRW] = (float (*)[CRW])(sm + OFF_DU);
    float (*s_dv)[CRW] = (float (*)[CRW])(sm + OFF_DV);
    float* s_red = sm + OFF_RED;

    const int tid = threadIdx.x;
    const int n   = blockIdx.z;
    const int tx0 = blockIdx.x * TX;
    const int ty0 = blockIdx.y * TY;
    const float* pin = inp + (size_t)n * IMG;
    const float* ptg = tgt + (size_t)n * IMG;

    // ---- Phase 1 ----
    bool interior = (tx0 >= 16) & (tx0 + TX + 16 <= WW) &
                    (ty0 >= 2*R) & (ty0 + TY + 2*R + 2 <= HH);
    if (interior) phase1<true >(pin, ptg, s_dy, s_du, s_dv, tx0, ty0, tid);
    else          phase1<false>(pin, ptg, s_dy, s_du, s_dv, tx0, ty0, tid);
    __syncthreads();

    // ---- Phase 2: vertical 15-tap running sums, in place (R6-verified windows) ----
    // dy region row i at stored row i+1; vy[r] = sum(stored r+8 .. r+22) -> stored row r.
    // Stored row x read at steps x-22 (+) and x-7 (-), both before its overwrite at step x.
    // Threads use CONSECUTIVE columns -> stride-1, conflict-free.
    if (tid < 142) {
        int c = tid + 9;
        float s = 0.f;
        #pragma unroll
        for (int j = 8; j <= 22; j++) s += s_dy[j][c];
        s_dy[0][c] = s;
        #pragma unroll 4
        for (int r = 1; r < TY; r++) {
            s += s_dy[r + 22][c] - s_dy[r + 7][c];
            s_dy[r][c] = s;
        }
    } else if (tid < 142 + 156) {     // chroma: 2 ch x 78 cols (cols 1..78)
        int t = tid - 142;
        int ch = (t >= 78);
        int c  = (ch ? t - 78 : t) + 1;
        float (*b)[CRW] = ch ? s_dv : s_du;
        float s = 0.f;
        #pragma unroll
        for (int j = 1; j <= 15; j++) s += b[j][c];
        b[0][c] = s;
        #pragma unroll 5
        for (int r = 1; r < TY/2; r++) {
            s += b[r + 15][c] - b[r][c];
            b[r][c] = s;
        }
    }
    __syncthreads();

    // ---- Phase 3: sliding 15-tap horizontal sums, lane = row (conflict-free) ----
    float accY = 0.f, accU = 0.f, accV = 0.f;
    const int w = tid >> 5, l = tid & 31;
    {   // luma: warp w covers output cols w*8..w*8+7; lane l = row l (FRW odd -> 1 wf/LDS)
        const float* rp = &s_dy[l][0];
        int c0 = w * 8 + 9;                 // window cols c0..c0+14
        float s = 0.f;
        #pragma unroll
        for (int j = 0; j < K; j++) s += rp[c0 + j];
        accY = s * s;
        #pragma unroll
        for (int i = 1; i < 8; i++) {
            s += rp[c0 + i + K - 1] - rp[c0 + i - 1];
            accY += s * s;
        }
    }
    {   // chroma: lanes 0-15 -> U rows 0-15; lanes 16-31 -> V rows 0-15
        int half = l >> 4, lr = l & 15;
        const float* rp = half ? &s_dv[lr][0] : &s_du[lr][0];
        int c0 = w * 4 + 1;                 // window cols c0..c0+14
        float s = 0.f;
        #pragma unroll
        for (int j = 0; j < K; j++) s += rp[c0 + j];
        float a = s * s;
        #pragma unroll
        for (int i = 1; i < 4; i++) {
            s += rp[c0 + i + K - 1] - rp[c0 + i - 1];
            a += s * s;
        }
        if (half) accV = a; else accU = a;
    }

    // ---- block reduction (16 warps) ----
    #pragma unroll
    for (int o = 16; o > 0; o >>= 1) {
        accY += __shfl_down_sync(0xffffffffu, accY, o);
        accU += __shfl_down_sync(0xffffffffu, accU, o);
        accV += __shfl_down_sync(0xffffffffu, accV, o);
    }
    if (l == 0) { s_red[w] = accY; s_red[16 + w] = accU; s_red[32 + w] = accV; }
    __syncthreads();
    if (tid == 0) {
        float sy = 0.f, su = 0.f, sv = 0.f;
        #pragma unroll
        for (int i = 0; i < 16; i++) { sy += s_red[i]; su += s_red[16+i]; sv += s_red[32+i]; }
        atomicAdd(&g_acc[0], sy);
        atomicAdd(&g_acc[1], su);
        atomicAdd(&g_acc[2], sv);
        __threadfence();
        unsigned int t = atomicAdd(&g_done, 1u);
        if (t == NBLK - 1) {
            const float invY = 1.0f / ((float)NB * HH * WW);
            const float invC = 1.0f / ((float)NB * (HH/2) * (WW/2));
            out[0] = g_acc[0] * invY + (g_acc[1] + g_acc[2]) * invC;
            g_acc[0] = 0.f; g_acc[1] = 0.f; g_acc[2] = 0.f;
            g_done = 0u;
        }
    }
}

extern "C" void kernel_launch(void* const* d_in, const int* in_sizes, int n_in,
                              void* d_out, int out_size)
{
    const float* inp = (const float*)d_in[0];
    const float* tgt = (const float*)d_in[1];
    float* out = (float*)d_out;

    static int configured = 0;
    if (!configured) {
        cudaFuncSetAttribute(yuv_loss_kernel,
                             cudaFuncAttributeMaxDynamicSharedMemorySize, SM_BYTES);
        configured = 1;
    }

    dim3 grid(GX, GY, NB);
    yuv_loss_kernel<<<grid, NTHR, SM_BYTES>>>(inp, tgt, out);
}